// round 1
// baseline (speedup 1.0000x reference)
#include <cuda_runtime.h>
#include <float.h>

// TropicalLinear: out[n,o] = bias[o] + max_k( x[n,k] + w[o,k] )
// N=128, IN=1024, OUT=1024, fp32.
//
// Phase 1: split-K tropical GEMM into partial-max scratch.
// Phase 2: reduce KSPLIT partials + bias -> out.

#define N_ROWS  128
#define IN_DIM  1024
#define OUT_DIM 1024

#define KSPLIT  16
#define KC      (IN_DIM / KSPLIT)   // 64
#define TN      64                  // CTA n-tile
#define TO      128                 // CTA o-tile
#define THREADS 256

// 16 * 128 * 1024 * 4B = 8 MB scratch for split-K partial maxes
__device__ float g_part[KSPLIT * N_ROWS * OUT_DIM];

__global__ __launch_bounds__(THREADS)
void tropical_phase1(const float* __restrict__ x, const float* __restrict__ w)
{
    // Transposed tiles: xs[k][n], ws[k][o]  (total 48 KB static smem)
    __shared__ float xs[KC * TN];
    __shared__ float ws[KC * TO];

    const int bo = blockIdx.x;            // 0..7   (o tile)
    const int bn = blockIdx.y;            // 0..1   (n tile)
    const int ks = blockIdx.z;            // 0..15  (k split)
    const int t  = threadIdx.x;

    const int n0 = bn * TN;
    const int o0 = bo * TO;
    const int k0 = ks * KC;

    // ---- fill xs[k][n]: lanes vary along n -> conflict-free STS ----
    {
        const int n  = t & 63;
        const int kq = t >> 6;            // 0..3, each covers 16 k
        const float4* xg =
            (const float4*)(x + (size_t)(n0 + n) * IN_DIM + k0 + kq * 16);
        #pragma unroll
        for (int j = 0; j < 4; j++) {
            float4 v = xg[j];
            int k = kq * 16 + j * 4;
            xs[(k + 0) * TN + n] = v.x;
            xs[(k + 1) * TN + n] = v.y;
            xs[(k + 2) * TN + n] = v.z;
            xs[(k + 3) * TN + n] = v.w;
        }
    }
    // ---- fill ws[k][o]: lanes vary along o -> conflict-free STS ----
    {
        const int o  = t & 127;
        const int kq = t >> 7;            // 0..1, each covers 32 k
        const float4* wg =
            (const float4*)(w + (size_t)(o0 + o) * IN_DIM + k0 + kq * 32);
        #pragma unroll
        for (int j = 0; j < 8; j++) {
            float4 v = wg[j];
            int k = kq * 32 + j * 4;
            ws[(k + 0) * TO + o] = v.x;
            ws[(k + 1) * TO + o] = v.y;
            ws[(k + 2) * TO + o] = v.z;
            ws[(k + 3) * TO + o] = v.w;
        }
    }
    __syncthreads();

    // Thread tile: 4 n x 8 o
    const int o_t = t & 15;               // 16 groups of 8 o
    const int n_t = t >> 4;               // 16 groups of 4 n

    float acc[4][8];
    #pragma unroll
    for (int i = 0; i < 4; i++)
        #pragma unroll
        for (int j = 0; j < 8; j++)
            acc[i][j] = -FLT_MAX;

    const float4* xs4 = (const float4*)xs;   // [KC][TN/4 = 16]
    const float4* ws4 = (const float4*)ws;   // [KC][TO/4 = 32]

    #pragma unroll 4
    for (int k = 0; k < KC; k++) {
        float4 xv = xs4[k * (TN / 4) + n_t];
        float4 wa = ws4[k * (TO / 4) + o_t * 2];
        float4 wb = ws4[k * (TO / 4) + o_t * 2 + 1];
        float ax[4] = {xv.x, xv.y, xv.z, xv.w};
        float aw[8] = {wa.x, wa.y, wa.z, wa.w, wb.x, wb.y, wb.z, wb.w};
        #pragma unroll
        for (int i = 0; i < 4; i++) {
            #pragma unroll
            for (int j = 0; j < 8; j++) {
                acc[i][j] = fmaxf(acc[i][j], ax[i] + aw[j]);
            }
        }
    }

    // ---- write partials: g_part[ks][n][o], float4 stores ----
    float* base = g_part
        + ((size_t)ks * N_ROWS + (n0 + n_t * 4)) * OUT_DIM
        + o0 + o_t * 8;
    #pragma unroll
    for (int i = 0; i < 4; i++) {
        float4 p0 = make_float4(acc[i][0], acc[i][1], acc[i][2], acc[i][3]);
        float4 p1 = make_float4(acc[i][4], acc[i][5], acc[i][6], acc[i][7]);
        float4* dst = (float4*)(base + (size_t)i * OUT_DIM);
        dst[0] = p0;
        dst[1] = p1;
    }
}

__global__ __launch_bounds__(THREADS)
void tropical_phase2(const float* __restrict__ bias, float* __restrict__ out)
{
    const int idx = blockIdx.x * THREADS + threadIdx.x;  // float4 index
    const int total4 = N_ROWS * OUT_DIM / 4;             // 32768
    if (idx >= total4) return;

    const float4* p4 = (const float4*)g_part;
    const int stride4 = N_ROWS * OUT_DIM / 4;

    float4 m = p4[idx];
    #pragma unroll
    for (int s = 1; s < KSPLIT; s++) {
        float4 v = p4[(size_t)s * stride4 + idx];
        m.x = fmaxf(m.x, v.x);
        m.y = fmaxf(m.y, v.y);
        m.z = fmaxf(m.z, v.z);
        m.w = fmaxf(m.w, v.w);
    }

    const int oq = idx & (OUT_DIM / 4 - 1);
    float4 b = ((const float4*)bias)[oq];
    m.x += b.x; m.y += b.y; m.z += b.z; m.w += b.w;

    ((float4*)out)[idx] = m;
}

extern "C" void kernel_launch(void* const* d_in, const int* in_sizes, int n_in,
                              void* d_out, int out_size)
{
    const float* x    = (const float*)d_in[0];   // [128, 1024]
    const float* w    = (const float*)d_in[1];   // [1024, 1024]
    const float* bias = (const float*)d_in[2];   // [1024]
    float* out = (float*)d_out;                  // [128, 1024]

    dim3 grid1(OUT_DIM / TO, N_ROWS / TN, KSPLIT);   // (8, 2, 16)
    tropical_phase1<<<grid1, THREADS>>>(x, w);

    int total4 = N_ROWS * OUT_DIM / 4;               // 32768
    tropical_phase2<<<(total4 + THREADS - 1) / THREADS, THREADS>>>(bias, out);
}